// round 12
// baseline (speedup 1.0000x reference)
#include <cuda_runtime.h>
#include <cuda_bf16.h>
#include <cstdint>
#include <math.h>

#define T_DIM 64
#define B_DIM 512
#define D_DIM 1536
#define H_DIM 1024
#define M_DIM (T_DIM * B_DIM)   // 32768
#define DISCOUNT 0.997f
#define LAM 0.95f

#define W_TOTAL (D_DIM * H_DIM + 3 * H_DIM * H_DIM)

// Scratch (allocation-free)
__device__ __nv_bfloat16 g_fhi [(size_t)M_DIM * D_DIM];
__device__ __nv_bfloat16 g_fmid[(size_t)M_DIM * D_DIM];
__device__ __nv_bfloat16 g_ahi [2][(size_t)M_DIM * H_DIM];
__device__ __nv_bfloat16 g_amid[2][(size_t)M_DIM * H_DIM];
__device__ __nv_bfloat16 g_whi [W_TOTAL];
__device__ __nv_bfloat16 g_wmid[W_TOTAL];
__device__ float g_partial[16 * (size_t)M_DIM];

// ---------------------------------------------------------------------------
// CTA tile 256(M) x 128(N), 8 warps 4m x 2n -> warp tile 64x64.
// smem per stage: A_hi/A_mid [256][40] bf16, B_hi/B_mid [128][40] bf16.
// 80B rows -> ldmatrix & cp.async conflict-free, 16B aligned.
// ---------------------------------------------------------------------------
#define STRIDE_H 40
#define A_PL 20480                       // 256*80
#define B_PL 10240                       // 128*80
#define OFF_AH 0
#define OFF_AM A_PL
#define OFF_BH (2 * A_PL)
#define OFF_BM (2 * A_PL + B_PL)
#define STAGE_B (2 * A_PL + 2 * B_PL)    // 61440
#define SMEM_BYTES (2 * STAGE_B)         // 122880

__device__ __forceinline__ uint32_t smem_to_u32(const void* p) {
    uint32_t a;
    asm("{ .reg .u64 t; cvta.to.shared.u64 t, %1; cvt.u32.u64 %0, t; }" : "=r"(a) : "l"(p));
    return a;
}
__device__ __forceinline__ float bf16_rn(float x) {
    return __bfloat162float(__float2bfloat16(x));
}
__device__ __forceinline__ uint32_t packbf(float lo, float hi) {
    uint32_t r;
    asm("cvt.rn.bf16x2.f32 %0, %1, %2;" : "=r"(r) : "f"(hi), "f"(lo));
    return r;
}
__device__ __forceinline__ float silu(float x) { return x / (1.0f + expf(-x)); }

__device__ __forceinline__ void mma16816(float* d, const uint32_t* a, const uint32_t* b) {
    asm volatile(
        "mma.sync.aligned.m16n8k16.row.col.f32.bf16.bf16.f32 "
        "{%0,%1,%2,%3}, {%4,%5,%6,%7}, {%8,%9}, {%0,%1,%2,%3};"
        : "+f"(d[0]), "+f"(d[1]), "+f"(d[2]), "+f"(d[3])
        : "r"(a[0]), "r"(a[1]), "r"(a[2]), "r"(a[3]), "r"(b[0]), "r"(b[1]));
}
#define LDSM4(r, addr) \
    asm volatile("ldmatrix.sync.aligned.m8n8.x4.shared.b16 {%0,%1,%2,%3}, [%4];" \
        : "=r"((r)[0]), "=r"((r)[1]), "=r"((r)[2]), "=r"((r)[3]) : "r"(addr))
#define CP16(dst, src) \
    asm volatile("cp.async.cg.shared.global [%0], [%1], 16;" :: "r"(dst), "l"(src))
#define CP_COMMIT asm volatile("cp.async.commit_group;" ::: "memory")
#define CP_WAIT0  asm volatile("cp.async.wait_group 0;" ::: "memory")

// ---------------------------------------------------------------------------
// splitter: fp32 -> bf16 hi/mid planes (flat layout) — proven R4 code
// ---------------------------------------------------------------------------
__global__ void __launch_bounds__(256)
split_kernel(const float* __restrict__ src, __nv_bfloat16* __restrict__ hi,
             __nv_bfloat16* __restrict__ mid, size_t n4)
{
    size_t i = (size_t)blockIdx.x * blockDim.x + threadIdx.x;
    const size_t stride = (size_t)gridDim.x * blockDim.x;
    const float4* s4 = (const float4*)src;
    uint32_t* h2 = (uint32_t*)hi;
    uint32_t* m2 = (uint32_t*)mid;
    for (; i < n4; i += stride) {
        float4 v = s4[i];
        float hx = bf16_rn(v.x), hy = bf16_rn(v.y), hz = bf16_rn(v.z), hw = bf16_rn(v.w);
        h2[i * 2]     = packbf(hx, hy);
        h2[i * 2 + 1] = packbf(hz, hw);
        m2[i * 2]     = packbf(v.x - hx, v.y - hy);
        m2[i * 2 + 1] = packbf(v.z - hz, v.w - hw);
    }
}

// ---------------------------------------------------------------------------
// weight splitter + transpose: W[K,N] fp32 -> Wt_hi/Wt_mid [N,K] bf16 (proven)
// ---------------------------------------------------------------------------
__global__ void __launch_bounds__(256)
split_wt_kernel(const float* __restrict__ W, __nv_bfloat16* __restrict__ whi,
                __nv_bfloat16* __restrict__ wmid, int K, int N)
{
    __shared__ float t[32][33];
    const int k0 = blockIdx.y * 32, n0 = blockIdx.x * 32;
    const int tx = threadIdx.x, ty = threadIdx.y;   // (32, 8)
    #pragma unroll
    for (int j = 0; j < 32; j += 8)
        t[ty + j][tx] = W[(size_t)(k0 + ty + j) * N + n0 + tx];
    __syncthreads();
    #pragma unroll
    for (int j = 0; j < 32; j += 8) {
        const float v = t[tx][ty + j];
        const float h = bf16_rn(v);
        const size_t o = (size_t)(n0 + ty + j) * K + k0 + tx;
        whi[o]  = __float2bfloat16(v);
        wmid[o] = __float2bfloat16(v - h);
    }
}

// ---------------------------------------------------------------------------
// GEMM: CTA 256x128, warp tile 64x64 (min smem bytes/MAC), planes streamed
// via cp.async 2-stage. mode 0: emit next-layer planes. mode 1: value head.
// ---------------------------------------------------------------------------
__global__ void __launch_bounds__(256)
gemm_hmma(const __nv_bfloat16* __restrict__ Ahi, const __nv_bfloat16* __restrict__ Amid,
          const __nv_bfloat16* __restrict__ Bhi, const __nv_bfloat16* __restrict__ Bmid,
          const float* __restrict__ bias,
          __nv_bfloat16* __restrict__ Chi, __nv_bfloat16* __restrict__ Cmid,
          const float* __restrict__ Wo, float* __restrict__ partial,
          int K, int mode)
{
    extern __shared__ char smem[];
    const uint32_t sbu = smem_to_u32(smem);
    const int tid  = threadIdx.x;
    const int wid  = tid >> 5;
    const int lane = tid & 31;
    const int row0 = blockIdx.y * 256;
    const int col0 = blockIdx.x * 128;
    const int wm = wid & 3;    // 4 m-warps
    const int wn = wid >> 2;   // 2 n-warps

    // ---- cp.async mappings ----
    // A: thread t owns row t (0..255): 4x16B per plane per chunk
    const __nv_bfloat16* pAh = Ahi  + (size_t)(row0 + tid) * K;
    const __nv_bfloat16* pAm = Amid + (size_t)(row0 + tid) * K;
    const uint32_t adst = (uint32_t)(tid * (STRIDE_H * 2));
    // B: 2 threads per row: 2x16B per plane per chunk
    const int r_b  = tid >> 1;
    const int sg_b = (tid & 1) * 2;
    const __nv_bfloat16* pBh = Bhi  + (size_t)(col0 + r_b) * K + sg_b * 8;
    const __nv_bfloat16* pBm = Bmid + (size_t)(col0 + r_b) * K + sg_b * 8;
    const uint32_t bdst = (uint32_t)(r_b * (STRIDE_H * 2) + sg_b * 16);

    float acc[4][8][4];
    #pragma unroll
    for (int i = 0; i < 4; i++)
        #pragma unroll
        for (int j = 0; j < 8; j++)
            #pragma unroll
            for (int c = 0; c < 4; c++) acc[i][j][c] = 0.0f;

    const int nk = K >> 5;

    auto issue = [&](int kt) {
        const uint32_t s = sbu + (kt & 1) * STAGE_B;
        const size_t ko = (size_t)kt * 32;
        #pragma unroll
        for (int j = 0; j < 4; j++) {
            CP16(s + OFF_AH + adst + j * 16, pAh + ko + j * 8);
            CP16(s + OFF_AM + adst + j * 16, pAm + ko + j * 8);
        }
        CP16(s + OFF_BH + bdst,      pBh + ko);
        CP16(s + OFF_BH + bdst + 16, pBh + ko + 8);
        CP16(s + OFF_BM + bdst,      pBm + ko);
        CP16(s + OFF_BM + bdst + 16, pBm + ko + 8);
    };

    // ---- prologue ----
    issue(0); CP_COMMIT;
    CP_WAIT0;
    __syncthreads();

    // ldmatrix lane addressing
    const int lm = lane >> 3;
    const int lr = lane & 7;
    const uint32_t a_lane = (uint32_t)((wm * 64 + (lm & 1) * 8 + lr) * (STRIDE_H * 2)
                                       + ((lm >> 1) * 8) * 2);
    const uint32_t b_lane = (uint32_t)((wn * 64 + (lm >> 1) * 8 + lr) * (STRIDE_H * 2)
                                       + ((lm & 1) * 8) * 2);

    for (int kt = 0; kt < nk; kt++) {
        const int buf = kt & 1;
        if (kt + 1 < nk) { issue(kt + 1); CP_COMMIT; }

        const uint32_t base = sbu + buf * STAGE_B;
        #pragma unroll
        for (int ks = 0; ks < 2; ks++) {
            const uint32_t ko = (uint32_t)(ks * 32);
            // load all B fragments for this warp's 64 columns (8 LDSM)
            uint32_t bfr[4][2][4];
            #pragma unroll
            for (int pr = 0; pr < 4; pr++) {
                const uint32_t bd = base + OFF_BH + b_lane
                                  + (uint32_t)(pr * 16 * STRIDE_H * 2) + ko;
                LDSM4(bfr[pr][0], bd);
                LDSM4(bfr[pr][1], bd + B_PL);
            }
            // per-mi: 2 LDSM + 24 MMA (R10/11 showed per-mi == batched)
            #pragma unroll
            for (int mi = 0; mi < 4; mi++) {
                const uint32_t ad = base + OFF_AH + a_lane
                                  + (uint32_t)(mi * 16 * STRIDE_H * 2) + ko;
                uint32_t ah[4], am[4];
                LDSM4(ah, ad);
                LDSM4(am, ad + A_PL);
                #pragma unroll
                for (int ni = 0; ni < 8; ni++)
                    mma16816(acc[mi][ni], ah, &bfr[ni >> 1][0][(ni & 1) * 2]);
                #pragma unroll
                for (int ni = 0; ni < 8; ni++)
                    mma16816(acc[mi][ni], ah, &bfr[ni >> 1][1][(ni & 1) * 2]);
                #pragma unroll
                for (int ni = 0; ni < 8; ni++)
                    mma16816(acc[mi][ni], am, &bfr[ni >> 1][0][(ni & 1) * 2]);
            }
        }

        if (kt + 1 < nk) {
            CP_WAIT0;
            __syncthreads();
        }
    }

    // ---- epilogue ----
    if (mode == 0) {
        #pragma unroll
        for (int mi = 0; mi < 4; mi++) {
            const int grow = row0 + wm * 64 + mi * 16 + (lane >> 2);
            #pragma unroll
            for (int ni = 0; ni < 8; ni++) {
                const int gcol = col0 + wn * 64 + ni * 8 + (lane & 3) * 2;
                const float bi0 = bias[gcol], bi1 = bias[gcol + 1];
                float x0 = silu(acc[mi][ni][0] + bi0);
                float x1 = silu(acc[mi][ni][1] + bi1);
                float x2 = silu(acc[mi][ni][2] + bi0);
                float x3 = silu(acc[mi][ni][3] + bi1);
                float h0 = bf16_rn(x0), h1 = bf16_rn(x1), h2 = bf16_rn(x2), h3 = bf16_rn(x3);
                const size_t o0 = (size_t)grow * H_DIM + gcol;
                const size_t o1 = (size_t)(grow + 8) * H_DIM + gcol;
                *(uint32_t*)(Chi  + o0) = packbf(h0, h1);
                *(uint32_t*)(Cmid + o0) = packbf(x0 - h0, x1 - h1);
                *(uint32_t*)(Chi  + o1) = packbf(h2, h3);
                *(uint32_t*)(Cmid + o1) = packbf(x2 - h2, x3 - h3);
            }
        }
    } else {
        const int p = blockIdx.x * 2 + wn;   // 16 partials
        #pragma unroll
        for (int mi = 0; mi < 4; mi++) {
            float s0 = 0.0f, s1 = 0.0f;
            #pragma unroll
            for (int ni = 0; ni < 8; ni++) {
                const int gcol = col0 + wn * 64 + ni * 8 + (lane & 3) * 2;
                const float bi0 = bias[gcol], bi1 = bias[gcol + 1];
                const float w0 = Wo[gcol], w1 = Wo[gcol + 1];
                s0 += silu(acc[mi][ni][0] + bi0) * w0 + silu(acc[mi][ni][1] + bi1) * w1;
                s1 += silu(acc[mi][ni][2] + bi0) * w0 + silu(acc[mi][ni][3] + bi1) * w1;
            }
            s0 += __shfl_xor_sync(0xffffffffu, s0, 1);
            s0 += __shfl_xor_sync(0xffffffffu, s0, 2);
            s1 += __shfl_xor_sync(0xffffffffu, s1, 1);
            s1 += __shfl_xor_sync(0xffffffffu, s1, 2);
            if ((lane & 3) == 0) {
                const int r = row0 + wm * 64 + mi * 16 + (lane >> 2);
                partial[(size_t)p * M_DIM + r]     = s0;
                partial[(size_t)p * M_DIM + r + 8] = s1;
            }
        }
    }
}

// ---------------------------------------------------------------------------
// GAE reverse scan; value[m] = sum of 16 partials + bo.
// ---------------------------------------------------------------------------
__global__ void __launch_bounds__(256)
scan_kernel(const float* __restrict__ reward, const float* __restrict__ cont,
            const float* __restrict__ partial, const float* __restrict__ bo,
            float* __restrict__ out)
{
    const int b = blockIdx.x * blockDim.x + threadIdx.x;
    if (b >= B_DIM) return;
    const float bov = bo[0];

    auto val = [&](int m) {
        float s = 0.0f;
        #pragma unroll
        for (int c = 0; c < 16; c++) s += partial[(size_t)c * M_DIM + m];
        return s + bov;
    };

    float adv = 0.0f;
    float v_next = val((T_DIM - 1) * B_DIM + b);
    for (int t = T_DIM - 2; t >= 0; t--) {
        const float v0   = val(t * B_DIM + b);
        const float disc = cont[(t + 1) * B_DIM + b] * DISCOUNT;
        const float dl   = disc * LAM;
        const float delta = reward[t * B_DIM + b] + disc * v_next - v0;
        adv = delta + dl * adv;
        out[t * B_DIM + b] = adv + v0;                       // ret
        out[(T_DIM - 1) * B_DIM + t * B_DIM + b] = v0;       // baseline
        v_next = v0;
    }
}

// ---------------------------------------------------------------------------
extern "C" void kernel_launch(void* const* d_in, const int* in_sizes, int n_in,
                              void* d_out, int out_size)
{
    const float* feat   = (const float*)d_in[0];
    const float* reward = (const float*)d_in[1];
    const float* cont   = (const float*)d_in[2];
    const float* W0 = (const float*)d_in[3];
    const float* b0 = (const float*)d_in[4];
    const float* W1 = (const float*)d_in[5];
    const float* b1 = (const float*)d_in[6];
    const float* W2 = (const float*)d_in[7];
    const float* b2 = (const float*)d_in[8];
    const float* W3 = (const float*)d_in[9];
    const float* b3 = (const float*)d_in[10];
    const float* Wo = (const float*)d_in[11];
    const float* bo = (const float*)d_in[12];
    float* out = (float*)d_out;

    __nv_bfloat16 *fhi, *fmid, *ahi, *amid, *whi, *wmid;
    float *part;
    cudaGetSymbolAddress((void**)&fhi,  g_fhi);
    cudaGetSymbolAddress((void**)&fmid, g_fmid);
    cudaGetSymbolAddress((void**)&ahi,  g_ahi);
    cudaGetSymbolAddress((void**)&amid, g_amid);
    cudaGetSymbolAddress((void**)&whi,  g_whi);
    cudaGetSymbolAddress((void**)&wmid, g_wmid);
    cudaGetSymbolAddress((void**)&part, g_partial);

    const size_t AH = (size_t)M_DIM * H_DIM;
    const size_t wo0 = 0;
    const size_t wo1 = (size_t)D_DIM * H_DIM;
    const size_t wo2 = wo1 + (size_t)H_DIM * H_DIM;
    const size_t wo3 = wo2 + (size_t)H_DIM * H_DIM;

    cudaFuncSetAttribute(gemm_hmma, cudaFuncAttributeMaxDynamicSharedMemorySize, SMEM_BYTES);

    // split feat + weights into bf16 hi/mid planes
    split_kernel<<<2048, 256>>>(feat, fhi, fmid, (size_t)M_DIM * D_DIM / 4);
    dim3 tb(32, 8);
    split_wt_kernel<<<dim3(H_DIM / 32, D_DIM / 32), tb>>>(W0, whi + wo0, wmid + wo0, D_DIM, H_DIM);
    split_wt_kernel<<<dim3(H_DIM / 32, H_DIM / 32), tb>>>(W1, whi + wo1, wmid + wo1, H_DIM, H_DIM);
    split_wt_kernel<<<dim3(H_DIM / 32, H_DIM / 32), tb>>>(W2, whi + wo2, wmid + wo2, H_DIM, H_DIM);
    split_wt_kernel<<<dim3(H_DIM / 32, H_DIM / 32), tb>>>(W3, whi + wo3, wmid + wo3, H_DIM, H_DIM);

    dim3 grid(H_DIM / 128, M_DIM / 256);   // (8, 128)
    gemm_hmma<<<grid, 256, SMEM_BYTES>>>(fhi, fmid, whi + wo0, wmid + wo0, b0,
                                         ahi, amid, nullptr, nullptr, D_DIM, 0);
    gemm_hmma<<<grid, 256, SMEM_BYTES>>>(ahi, amid, whi + wo1, wmid + wo1, b1,
                                         ahi + AH, amid + AH, nullptr, nullptr, H_DIM, 0);
    gemm_hmma<<<grid, 256, SMEM_BYTES>>>(ahi + AH, amid + AH, whi + wo2, wmid + wo2, b2,
                                         ahi, amid, nullptr, nullptr, H_DIM, 0);
    gemm_hmma<<<grid, 256, SMEM_BYTES>>>(ahi, amid, whi + wo3, wmid + wo3, b3,
                                         nullptr, nullptr, Wo, part, H_DIM, 1);
    scan_kernel<<<2, 256>>>(reward, cont, part, bo, out);
}

// round 13
// speedup vs baseline: 1.3655x; 1.3655x over previous
#include <cuda_runtime.h>
#include <cuda_bf16.h>
#include <cstdint>
#include <math.h>

#define T_DIM 64
#define B_DIM 512
#define D_DIM 1536
#define H_DIM 1024
#define M_DIM (T_DIM * B_DIM)   // 32768
#define DISCOUNT 0.997f
#define LAM 0.95f

#define W_TOTAL (D_DIM * H_DIM + 3 * H_DIM * H_DIM)

// Scratch (allocation-free)
__device__ float g_buf0[(size_t)M_DIM * H_DIM];
__device__ float g_buf1[(size_t)M_DIM * H_DIM];
__device__ __nv_bfloat16 g_whi [W_TOTAL];   // weights transposed [N,K], hi plane
__device__ __nv_bfloat16 g_wmid[W_TOTAL];   // mid plane
__device__ float g_partial[32 * (size_t)M_DIM];

// ---------------------------------------------------------------------------
// smem per stage: A_hi, A_mid, B_hi, B_mid each [128][40] bf16 (stride 40
// halves = 80B rows -> LDS/ldmatrix/cp.async dst all conflict-free, 16B-aligned).
// ---------------------------------------------------------------------------
#define STRIDE_H 40
#define TILE_B 10240                     // 128 * 40 * 2
#define OFF_AH 0
#define OFF_AM TILE_B
#define OFF_BH (2 * TILE_B)
#define OFF_BM (3 * TILE_B)
#define STAGE_B (4 * TILE_B)             // 40960
#define SMEM_BYTES (2 * STAGE_B)         // 81920

__device__ __forceinline__ uint32_t smem_to_u32(const void* p) {
    uint32_t a;
    asm("{ .reg .u64 t; cvta.to.shared.u64 t, %1; cvt.u32.u64 %0, t; }" : "=r"(a) : "l"(p));
    return a;
}
__device__ __forceinline__ float bf16_rn(float x) {
    return __bfloat162float(__float2bfloat16(x));
}
__device__ __forceinline__ uint32_t packbf(float lo, float hi) {
    uint32_t r;
    asm("cvt.rn.bf16x2.f32 %0, %1, %2;" : "=r"(r) : "f"(hi), "f"(lo));
    return r;
}
__device__ __forceinline__ float silu(float x) { return x / (1.0f + expf(-x)); }

__device__ __forceinline__ void mma16816(float* d, const uint32_t* a, const uint32_t* b) {
    asm volatile(
        "mma.sync.aligned.m16n8k16.row.col.f32.bf16.bf16.f32 "
        "{%0,%1,%2,%3}, {%4,%5,%6,%7}, {%8,%9}, {%0,%1,%2,%3};"
        : "+f"(d[0]), "+f"(d[1]), "+f"(d[2]), "+f"(d[3])
        : "r"(a[0]), "r"(a[1]), "r"(a[2]), "r"(a[3]), "r"(b[0]), "r"(b[1]));
}
#define LDSM4(r, addr) \
    asm volatile("ldmatrix.sync.aligned.m8n8.x4.shared.b16 {%0,%1,%2,%3}, [%4];" \
        : "=r"((r)[0]), "=r"((r)[1]), "=r"((r)[2]), "=r"((r)[3]) : "r"(addr))
#define CP16(dst, src) \
    asm volatile("cp.async.cg.shared.global [%0], [%1], 16;" :: "r"(dst), "l"(src))
#define CP_COMMIT asm volatile("cp.async.commit_group;" ::: "memory")
#define CP_WAIT0  asm volatile("cp.async.wait_group 0;" ::: "memory")

// ---------------------------------------------------------------------------
// weight splitter + transpose: W[K,N] fp32 -> Wt_hi/Wt_mid [N,K] bf16 (proven)
// ---------------------------------------------------------------------------
__global__ void __launch_bounds__(256)
split_wt_kernel(const float* __restrict__ W, __nv_bfloat16* __restrict__ whi,
                __nv_bfloat16* __restrict__ wmid, int K, int N)
{
    __shared__ float t[32][33];
    const int k0 = blockIdx.y * 32, n0 = blockIdx.x * 32;
    const int tx = threadIdx.x, ty = threadIdx.y;   // (32, 8)
    #pragma unroll
    for (int j = 0; j < 32; j += 8)
        t[ty + j][tx] = W[(size_t)(k0 + ty + j) * N + n0 + tx];
    __syncthreads();
    #pragma unroll
    for (int j = 0; j < 32; j += 8) {
        const float v = t[tx][ty + j];
        const float h = bf16_rn(v);
        const size_t o = (size_t)(n0 + ty + j) * K + k0 + tx;
        whi[o]  = __float2bfloat16(v);
        wmid[o] = __float2bfloat16(v - h);
    }
}

// ---------------------------------------------------------------------------
// GEMM: 128x128 tile, 8 warps (2m x 4n, warp tile 64x32), 3xBF16 split mma.
// A: fp32 LDG register-prefetched at loop top (latency hidden by compute),
//    split+STS after compute (short tail). B: pre-split planes via cp.async.
// 2 CTAs/SM. mode 0: fp32 activations out. mode 1: fused value head.
// ---------------------------------------------------------------------------
__global__ void __launch_bounds__(256, 2)
gemm_hmma(const float* __restrict__ A,
          const __nv_bfloat16* __restrict__ Bhi, const __nv_bfloat16* __restrict__ Bmid,
          const float* __restrict__ bias, float* __restrict__ C,
          const float* __restrict__ Wo, float* __restrict__ partial,
          int K, int mode)
{
    extern __shared__ char smem[];
    const uint32_t sbu = smem_to_u32(smem);
    const int tid  = threadIdx.x;
    const int wid  = tid >> 5;
    const int lane = tid & 31;
    const int row0 = blockIdx.y * 128;
    const int col0 = blockIdx.x * 128;
    const int wm = wid & 1;
    const int wn = wid >> 1;

    // ---- A global-load mapping: 4 rows x 4 floats per thread ----
    const int m_a  = tid >> 3;            // row 0..31 (+32*it)
    const int kc_a = (tid & 7) * 4;       // k-float 0..28
    const float* Aptr = A + (size_t)(row0 + m_a) * K + kc_a;

    // ---- B cp.async mapping: 2x16B per plane per thread ----
    const int r_b  = tid >> 1;            // B row (n) 0..127
    const int sg_b = (tid & 1) * 2;       // 16B segment base {0,2}
    const __nv_bfloat16* pBh = Bhi  + (size_t)(col0 + r_b) * K + sg_b * 8;
    const __nv_bfloat16* pBm = Bmid + (size_t)(col0 + r_b) * K + sg_b * 8;
    const uint32_t bdst = (uint32_t)(r_b * (STRIDE_H * 2) + sg_b * 16);

    float acc[4][4][4];
    #pragma unroll
    for (int i = 0; i < 4; i++)
        #pragma unroll
        for (int j = 0; j < 4; j++)
            #pragma unroll
            for (int c = 0; c < 4; c++) acc[i][j][c] = 0.0f;

    const int nk = K >> 5;
    float4 av[4];   // A register prefetch

    auto issueB = [&](int kt) {
        const uint32_t d = sbu + (kt & 1) * STAGE_B + bdst;
        const size_t ko = (size_t)kt * 32;
        CP16(d + OFF_BH,      pBh + ko);
        CP16(d + OFF_BH + 16, pBh + ko + 8);
        CP16(d + OFF_BM,      pBm + ko);
        CP16(d + OFF_BM + 16, pBm + ko + 8);
    };

    auto load_av = [&](int kt) {
        #pragma unroll
        for (int it = 0; it < 4; it++)
            av[it] = *(const float4*)(Aptr + (size_t)(32 * it) * K + kt * 32);
    };

    auto split_sts_A = [&](int kt) {
        uint32_t* Ah = (uint32_t*)(smem + (kt & 1) * STAGE_B + OFF_AH);
        uint32_t* Am = (uint32_t*)(smem + (kt & 1) * STAGE_B + OFF_AM);
        #pragma unroll
        for (int it = 0; it < 4; it++) {
            const int idx = ((m_a + 32 * it) * STRIDE_H + kc_a) >> 1;
            float hx = bf16_rn(av[it].x), hy = bf16_rn(av[it].y);
            float hz = bf16_rn(av[it].z), hw = bf16_rn(av[it].w);
            Ah[idx]     = packbf(hx, hy);
            Ah[idx + 1] = packbf(hz, hw);
            Am[idx]     = packbf(av[it].x - hx, av[it].y - hy);
            Am[idx + 1] = packbf(av[it].z - hz, av[it].w - hw);
        }
    };

    // ---- prologue ----
    issueB(0); CP_COMMIT;
    load_av(0);
    split_sts_A(0);
    CP_WAIT0;
    __syncthreads();

    // ldmatrix lane addresses (proven mapping)
    const int lm = lane >> 3;
    const int lr = lane & 7;
    const uint32_t a_lane = (uint32_t)((wm * 64 + (lm & 1) * 8 + lr) * (STRIDE_H * 2)
                                       + ((lm >> 1) * 8) * 2);
    const uint32_t b_lane = (uint32_t)((wn * 32 + (lm >> 1) * 8 + lr) * (STRIDE_H * 2)
                                       + ((lm & 1) * 8) * 2);

    for (int kt = 0; kt < nk; kt++) {
        const int buf = kt & 1;
        // prefetch next chunk: B via cp.async, A via LDG into registers —
        // both issued BEFORE compute so latency hides behind the MMA passes.
        if (kt + 1 < nk) {
            issueB(kt + 1); CP_COMMIT;
            load_av(kt + 1);
        }

        const uint32_t base = sbu + buf * STAGE_B;
        #pragma unroll
        for (int ks = 0; ks < 2; ks++) {
            const uint32_t ko = (uint32_t)(ks * 32);
            uint32_t bfr[2][2][4];
            #pragma unroll
            for (int pr = 0; pr < 2; pr++) {
                const uint32_t bd = base + OFF_BH + b_lane
                                  + (uint32_t)(pr * 16 * STRIDE_H * 2) + ko;
                LDSM4(bfr[pr][0], bd);
                LDSM4(bfr[pr][1], bd + TILE_B);
            }
            // per-mi A fragments (R10/11: equal perf, frees 24 registers)
            #pragma unroll
            for (int mi = 0; mi < 4; mi++) {
                const uint32_t ad = base + OFF_AH + a_lane
                                  + (uint32_t)(mi * 16 * STRIDE_H * 2) + ko;
                uint32_t ah[4], am[4];
                LDSM4(ah, ad);
                LDSM4(am, ad + TILE_B);
                #pragma unroll
                for (int ni = 0; ni < 4; ni++)
                    mma16816(acc[mi][ni], ah, &bfr[ni >> 1][0][(ni & 1) * 2]);
                #pragma unroll
                for (int ni = 0; ni < 4; ni++)
                    mma16816(acc[mi][ni], ah, &bfr[ni >> 1][1][(ni & 1) * 2]);
                #pragma unroll
                for (int ni = 0; ni < 4; ni++)
                    mma16816(acc[mi][ni], am, &bfr[ni >> 1][0][(ni & 1) * 2]);
            }
        }

        if (kt + 1 < nk) {
            split_sts_A(kt + 1);   // short tail: cvt + STS only, LDG already landed
            CP_WAIT0;
            __syncthreads();
        }
    }

    // ---- epilogue (R9) ----
    if (mode == 0) {
        #pragma unroll
        for (int mi = 0; mi < 4; mi++) {
            const int grow = row0 + wm * 64 + mi * 16 + (lane >> 2);
            #pragma unroll
            for (int ni = 0; ni < 4; ni++) {
                const int gcol = col0 + wn * 32 + ni * 8 + (lane & 3) * 2;
                const float bi0 = bias[gcol], bi1 = bias[gcol + 1];
                float2 v0, v1;
                v0.x = silu(acc[mi][ni][0] + bi0);
                v0.y = silu(acc[mi][ni][1] + bi1);
                v1.x = silu(acc[mi][ni][2] + bi0);
                v1.y = silu(acc[mi][ni][3] + bi1);
                *(float2*)&C[(size_t)grow * H_DIM + gcol]       = v0;
                *(float2*)&C[(size_t)(grow + 8) * H_DIM + gcol] = v1;
            }
        }
    } else {
        const int p = blockIdx.x * 4 + wn;
        #pragma unroll
        for (int mi = 0; mi < 4; mi++) {
            float s0 = 0.0f, s1 = 0.0f;
            #pragma unroll
            for (int ni = 0; ni < 4; ni++) {
                const int gcol = col0 + wn * 32 + ni * 8 + (lane & 3) * 2;
                const float bi0 = bias[gcol], bi1 = bias[gcol + 1];
                const float w0 = Wo[gcol], w1 = Wo[gcol + 1];
                s0 += silu(acc[mi][ni][0] + bi0) * w0 + silu(acc[mi][ni][1] + bi1) * w1;
                s1 += silu(acc[mi][ni][2] + bi0) * w0 + silu(acc[mi][ni][3] + bi1) * w1;
            }
            s0 += __shfl_xor_sync(0xffffffffu, s0, 1);
            s0 += __shfl_xor_sync(0xffffffffu, s0, 2);
            s1 += __shfl_xor_sync(0xffffffffu, s1, 1);
            s1 += __shfl_xor_sync(0xffffffffu, s1, 2);
            if ((lane & 3) == 0) {
                const int r = row0 + wm * 64 + mi * 16 + (lane >> 2);
                partial[(size_t)p * M_DIM + r]     = s0;
                partial[(size_t)p * M_DIM + r + 8] = s1;
            }
        }
    }
}

// ---------------------------------------------------------------------------
// GAE reverse scan; value[m] = sum of 32 partials + bo.
// ---------------------------------------------------------------------------
__global__ void __launch_bounds__(256)
scan_kernel(const float* __restrict__ reward, const float* __restrict__ cont,
            const float* __restrict__ partial, const float* __restrict__ bo,
            float* __restrict__ out)
{
    const int b = blockIdx.x * blockDim.x + threadIdx.x;
    if (b >= B_DIM) return;
    const float bov = bo[0];

    auto val = [&](int m) {
        float s = 0.0f;
        #pragma unroll
        for (int c = 0; c < 32; c++) s += partial[(size_t)c * M_DIM + m];
        return s + bov;
    };

    float adv = 0.0f;
    float v_next = val((T_DIM - 1) * B_DIM + b);
    for (int t = T_DIM - 2; t >= 0; t--) {
        const float v0   = val(t * B_DIM + b);
        const float disc = cont[(t + 1) * B_DIM + b] * DISCOUNT;
        const float dl   = disc * LAM;
        const float delta = reward[t * B_DIM + b] + disc * v_next - v0;
        adv = delta + dl * adv;
        out[t * B_DIM + b] = adv + v0;                       // ret
        out[(T_DIM - 1) * B_DIM + t * B_DIM + b] = v0;       // baseline
        v_next = v0;
    }
}

// ---------------------------------------------------------------------------
extern "C" void kernel_launch(void* const* d_in, const int* in_sizes, int n_in,
                              void* d_out, int out_size)
{
    const float* feat   = (const float*)d_in[0];
    const float* reward = (const float*)d_in[1];
    const float* cont   = (const float*)d_in[2];
    const float* W0 = (const float*)d_in[3];
    const float* b0 = (const float*)d_in[4];
    const float* W1 = (const float*)d_in[5];
    const float* b1 = (const float*)d_in[6];
    const float* W2 = (const float*)d_in[7];
    const float* b2 = (const float*)d_in[8];
    const float* W3 = (const float*)d_in[9];
    const float* b3 = (const float*)d_in[10];
    const float* Wo = (const float*)d_in[11];
    const float* bo = (const float*)d_in[12];
    float* out = (float*)d_out;

    float *buf0, *buf1, *part;
    __nv_bfloat16 *whi, *wmid;
    cudaGetSymbolAddress((void**)&buf0, g_buf0);
    cudaGetSymbolAddress((void**)&buf1, g_buf1);
    cudaGetSymbolAddress((void**)&whi,  g_whi);
    cudaGetSymbolAddress((void**)&wmid, g_wmid);
    cudaGetSymbolAddress((void**)&part, g_partial);

    const size_t wo0 = 0;
    const size_t wo1 = (size_t)D_DIM * H_DIM;
    const size_t wo2 = wo1 + (size_t)H_DIM * H_DIM;
    const size_t wo3 = wo2 + (size_t)H_DIM * H_DIM;

    cudaFuncSetAttribute(gemm_hmma, cudaFuncAttributeMaxDynamicSharedMemorySize, SMEM_BYTES);

    dim3 tb(32, 8);
    split_wt_kernel<<<dim3(H_DIM / 32, D_DIM / 32), tb>>>(W0, whi + wo0, wmid + wo0, D_DIM, H_DIM);
    split_wt_kernel<<<dim3(H_DIM / 32, H_DIM / 32), tb>>>(W1, whi + wo1, wmid + wo1, H_DIM, H_DIM);
    split_wt_kernel<<<dim3(H_DIM / 32, H_DIM / 32), tb>>>(W2, whi + wo2, wmid + wo2, H_DIM, H_DIM);
    split_wt_kernel<<<dim3(H_DIM / 32, H_DIM / 32), tb>>>(W3, whi + wo3, wmid + wo3, H_DIM, H_DIM);

    dim3 grid(H_DIM / 128, M_DIM / 128);   // (8, 256)
    gemm_hmma<<<grid, 256, SMEM_BYTES>>>(feat, whi + wo0, wmid + wo0, b0, buf0,
                                         nullptr, nullptr, D_DIM, 0);
    gemm_hmma<<<grid, 256, SMEM_BYTES>>>(buf0, whi + wo1, wmid + wo1, b1, buf1,
                                         nullptr, nullptr, H_DIM, 0);
    gemm_hmma<<<grid, 256, SMEM_BYTES>>>(buf1, whi + wo2, wmid + wo2, b2, buf0,
                                         nullptr, nullptr, H_DIM, 0);
    gemm_hmma<<<grid, 256, SMEM_BYTES>>>(buf0, whi + wo3, wmid + wo3, b3, nullptr,
                                         Wo, part, H_DIM, 1);
    scan_kernel<<<2, 256>>>(reward, cont, part, bo, out);
}